// round 15
// baseline (speedup 1.0000x reference)
#include <cuda_runtime.h>

#define BS    64
#define SL    8192
#define EDIM  64
#define DDIM  64
#define VOCAB 1088
#define NVAL  64
#define NTILE 17
#define SPLIT 4
#define CHUNK (SL / SPLIT)          // 2048
#define ATHR  512
#define AWARPS (ATHR / 32)          // 16
#define EPT   4

// Scratch (no allocations allowed)
__device__ float g_Qk[BS * EDIM];
__device__ float g_EV[BS * NVAL];
__device__ float g_EK[BS * VOCAB];
__device__ float g_num[BS * NVAL];   // zero-init; reset by combining block
__device__ int   g_cnt[BS];          // zero-init; reset by combining block

// ---------------------------------------------------------------------------
// A1: Q, Qk, EV per batch. 64 blocks x 256 threads. (R14 version, measured.)
// ---------------------------------------------------------------------------
__global__ __launch_bounds__(256) void qk_kernel(
    const int*   __restrict__ q,
    const float* __restrict__ embK,
    const float* __restrict__ Wk_w,   // (64, 128) row-major
    const float* __restrict__ Wq_w,   // (64, 64) row-major
    const float* __restrict__ Wq_b)
{
    const int b   = blockIdx.x;
    const int tid = threadIdx.x;

    __shared__ float eqs[EDIM];
    __shared__ float Qs [DDIM];
    __shared__ float part[256];

    const int qi = q[b];

    const int d_q = tid >> 2, s_q = tid & 3;
    float4 wq[4];
    {
        const float4* wrow = reinterpret_cast<const float4*>(
            Wq_w + (size_t)d_q * EDIM + s_q * 16);
        #pragma unroll
        for (int i = 0; i < 4; i++) wq[i] = wrow[i];
    }
    const int c  = tid & 127, hh = tid >> 7;
    float wk[32];
    {
        const float* base = Wk_w + (size_t)hh * 32 * 128 + c;
        #pragma unroll
        for (int i = 0; i < 32; i++) wk[i] = base[(size_t)i * 128];
    }
    const float wqb = (tid < DDIM) ? Wq_b[tid] : 0.f;

    if (tid < EDIM) eqs[tid] = embK[(size_t)qi * EDIM + tid];
    __syncthreads();

    {
        float acc = 0.f;
        #pragma unroll
        for (int i = 0; i < 4; i++) {
            const int e = s_q * 16 + i * 4;
            acc += wq[i].x * eqs[e]     + wq[i].y * eqs[e + 1]
                 + wq[i].z * eqs[e + 2] + wq[i].w * eqs[e + 3];
        }
        part[tid] = acc;
    }
    __syncthreads();
    if (tid < DDIM)
        Qs[tid] = part[tid * 4] + part[tid * 4 + 1]
                + part[tid * 4 + 2] + part[tid * 4 + 3] + wqb;
    __syncthreads();

    {
        float acc = 0.f;
        #pragma unroll
        for (int i = 0; i < 32; i++)
            acc = fmaf(wk[i], Qs[hh * 32 + i], acc);
        part[tid] = acc;
    }
    __syncthreads();
    if (tid < 128) {
        const float val = (part[tid] + part[tid + 128]) * 0.125f;
        if (tid < NVAL) g_EV[b * NVAL + tid] = __expf(val);
        else            g_Qk[b * EDIM + (tid - NVAL)] = val;
    }
}

// ---------------------------------------------------------------------------
// A2: EK. 64 batches x 17 tiles = 1088 blocks, 128 threads. (R11, measured.)
// ---------------------------------------------------------------------------
__global__ __launch_bounds__(128) void ek_kernel(const float* __restrict__ embK)
{
    const int bid  = blockIdx.x;
    const int b    = bid / NTILE;
    const int tile = bid % NTILE;
    const int v0   = tile * 64;
    const int tid  = threadIdx.x;
    const int v    = tid & 63;
    const int h    = tid >> 6;

    __shared__ float qks[EDIM];
    __shared__ float tl[64 * 65];
    __shared__ float part[128];

    if (tid < EDIM) qks[tid] = g_Qk[b * EDIM + tid];
    {
        const float4* src = reinterpret_cast<const float4*>(embK + (size_t)v0 * EDIM);
        for (int i = tid; i < 1024; i += 128) {
            const float4 val = src[i];
            float* d = &tl[(i >> 4) * 65 + (i & 15) * 4];
            d[0] = val.x; d[1] = val.y; d[2] = val.z; d[3] = val.w;
        }
    }
    __syncthreads();

    float acc = 0.f;
    #pragma unroll
    for (int i = 0; i < 32; i++)
        acc = fmaf(tl[v * 65 + h * 32 + i], qks[h * 32 + i], acc);
    part[tid] = acc;
    __syncthreads();

    if (tid < 64)
        g_EK[(size_t)b * VOCAB + v0 + tid] = __expf(part[tid] + part[tid + 64]);
}

// ---------------------------------------------------------------------------
// Kernel B: gather-histogram. SPLIT=4, 512 threads — same per-thread work as
// R11 (EPT=4, warp-replicated bins, REDG epilogue) but HALF the blocks, so
// half the per-block fixed costs (fill/sync/epilogue) and combine fan-in.
// ---------------------------------------------------------------------------
__global__ __launch_bounds__(ATHR) void attn_kernel(
    const int* __restrict__ x,
    float*     __restrict__ out)
{
    const int b    = blockIdx.x >> 2;
    const int sp   = blockIdx.x & 3;
    const int tid  = threadIdx.x;
    const int warp = tid >> 5;

    __shared__ float EKs[VOCAB];
    __shared__ float bins[AWARPS][NVAL];
    __shared__ float num[NVAL];
    __shared__ float rcpZ;
    __shared__ int   lastFlag;

    // Prefetch index data first (DRAM) — overlaps table fill (L2)
    const int* kp = x + (size_t)b * 2 * SL + sp * CHUNK;
    const int* vp = kp + SL;
    const int4 k4 = __ldg(reinterpret_cast<const int4*>(kp) + tid);
    const int4 w4 = __ldg(reinterpret_cast<const int4*>(vp) + tid);

    // EK table fill (vectorized, from L2)
    {
        const float4* src = reinterpret_cast<const float4*>(g_EK + (size_t)b * VOCAB);
        float4* dst = reinterpret_cast<float4*>(EKs);
        for (int i = tid; i < VOCAB / 4; i += ATHR) dst[i] = src[i];
    }
    for (int i = tid; i < AWARPS * NVAL; i += ATHR) (&bins[0][0])[i] = 0.f;
    __syncthreads();

    const int kk[EPT] = {k4.x, k4.y, k4.z, k4.w};
    const int vv[EPT] = {w4.x - NVAL, w4.y - NVAL, w4.z - NVAL, w4.w - NVAL};

    #pragma unroll
    for (int i = 0; i < EPT; i++)
        atomicAdd(&bins[warp][vv[i]], EKs[kk[i]]);
    __syncthreads();

    // Block bins -> global accumulator (REDG)
    if (tid < NVAL) {
        float bsum = 0.f;
        #pragma unroll
        for (int w = 0; w < AWARPS; w++) bsum += bins[w][tid];
        atomicAdd(&g_num[b * NVAL + tid], bsum);
    }
    __syncthreads();

    if (tid == 0) {
        __threadfence();
        const int old = atomicAdd(&g_cnt[b], 1);
        lastFlag = (old == SPLIT - 1) ? 1 : 0;
        __threadfence();
    }
    __syncthreads();

    if (lastFlag) {
        if (tid < NVAL) {
            volatile float* vnum = g_num + b * NVAL;
            num[tid] = vnum[tid] * g_EV[b * NVAL + tid];
        }
        __syncthreads();
        if (tid < 32) {
            float zz = num[tid] + num[tid + 32];
            #pragma unroll
            for (int o = 16; o > 0; o >>= 1) zz += __shfl_xor_sync(0xffffffffu, zz, o);
            if (tid == 0) rcpZ = __frcp_rn(zz);
        }
        __syncthreads();
        if (tid < NVAL) {
            out[b * NVAL + tid] = num[tid] * rcpZ;
            g_num[b * NVAL + tid] = 0.f;            // re-arm accumulator
        }
        __syncthreads();
        if (tid == 0) g_cnt[b] = 0;                 // re-arm counter
    }
}

// ---------------------------------------------------------------------------
// Inputs (metadata order): x(int32), q(int32), embK, Wk_w, Wk_b, Wq_w, Wq_b.
// Wk_b is softmax-invariant (constant per batch) and intentionally unused.
// ---------------------------------------------------------------------------
extern "C" void kernel_launch(void* const* d_in, const int* in_sizes, int n_in,
                              void* d_out, int out_size)
{
    const int*   x    = (const int*)  d_in[0];
    const int*   q    = (const int*)  d_in[1];
    const float* embK = (const float*)d_in[2];
    const float* Wk_w = (const float*)d_in[3];
    const float* Wq_w = (const float*)d_in[5];
    const float* Wq_b = (const float*)d_in[6];
    float* out = (float*)d_out;

    qk_kernel<<<BS, 256>>>(q, embK, Wk_w, Wq_w, Wq_b);
    ek_kernel<<<BS * NTILE, 128>>>(embK);
    attn_kernel<<<BS * SPLIT, ATHR>>>(x, out);
}